// round 16
// baseline (speedup 1.0000x reference)
#include <cuda_runtime.h>
#include <cuda_fp16.h>
#include <cstdint>

#define BB 2
#define SS 4096
#define DD 128
#define HALF 64
#define TM 64            // rows per CTA
#define KU 192           // key union
#define NT 256           // 8 warps

// only K and V^T need global visibility (halo exchange); Q stays in smem
__device__ __half g_k[BB * SS * DD];
__device__ __half g_vt[BB * DD * SS];
__device__ int    g_flag[BB * 64];    // returns to 0 every launch

__device__ __forceinline__ uint32_t pkh(float a, float b) {
    __half2 h = __floats2half2_rn(a, b);
    return *(uint32_t*)&h;
}
__device__ __forceinline__ uint32_t smem_u32(const void* p) {
    uint32_t a;
    asm("{ .reg .u64 t; cvta.to.shared.u64 t, %1; cvt.u32.u64 %0, t; }" : "=r"(a) : "l"(p));
    return a;
}
__device__ __forceinline__ void cpa(uint32_t dst, const void* src, int srcsz) {
    asm volatile("cp.async.cg.shared.global [%0], [%1], 16, %2;"
                 :: "r"(dst), "l"(src), "r"(srcsz) : "memory");
}
#define CP_COMMIT() asm volatile("cp.async.commit_group;" ::: "memory")
#define CP_WAIT(n)  asm volatile("cp.async.wait_group %0;" :: "n"(n) : "memory")

__device__ __forceinline__ void mma16(float* c, const uint32_t* a, uint32_t b0, uint32_t b1) {
    asm volatile(
        "mma.sync.aligned.m16n8k16.row.col.f32.f16.f16.f32 "
        "{%0,%1,%2,%3}, {%4,%5,%6,%7}, {%8,%9}, {%0,%1,%2,%3};"
        : "+f"(c[0]), "+f"(c[1]), "+f"(c[2]), "+f"(c[3])
        : "r"(a[0]), "r"(a[1]), "r"(a[2]), "r"(a[3]), "r"(b0), "r"(b1));
}

// word pitches (all ≡ 4 mod 32 -> conflict-free fragment loads)
#define XPF 132   // X fp32
#define HP  68    // Q/K/Wt fp16 (=136 halves)
#define VTP 100   // Vt / P fp16 (=200 halves)

// smem word offsets (aliasing by liveness):
//  Xs [0,8448) dead after A-frag cache; P [0,6400)+rs [6400,6528) written post-MMA1
//  Wt0 [8448,17152) dead after Q-MMA; Qh [8448,12800) written after
//  Vt [12800,25600) written after V-MMA (over Wt0 tail + Wt1)
//  Wt1 [17152,25856) dead after K-MMA;  Wt2 [25856,34560) dead after V-MMA
//  Kh [34560,47616) own region
#define XS_OFF  0
#define PH_OFF  0
#define RS_OFF  6400
#define QH_OFF  8448
#define WT0_OFF 8448
#define VT_OFF  12800
#define WT1_OFF 17152
#define WT2_OFF 25856
#define KH_OFF  34560
#define SMEM_W  47616
#define SMEM_BYTES (SMEM_W * 4)   // 190464

__global__ __launch_bounds__(NT, 1) void fused_kernel(
    const float* __restrict__ x,
    const float* __restrict__ Wq, const float* __restrict__ bq,
    const float* __restrict__ Wk, const float* __restrict__ bk,
    const float* __restrict__ Wv, const float* __restrict__ bv,
    float* __restrict__ out)
{
    extern __shared__ uint32_t sm[];
    const uint32_t sb = smem_u32(sm);

    const int tid = threadIdx.x, w = tid >> 5, lane = tid & 31;
    const int gy = lane >> 2, gx = lane & 3;
    const int b  = blockIdx.x >> 6;
    const int tb = blockIdx.x & 63;
    const int q0 = tb * TM;
    const int kb = q0 - HALF;
    const int r0 = 16 * (w & 3);
    const int c0 = 64 * (w >> 2);

    // ---- stage X (cp.async) ----
    for (int i = tid; i < TM * 32; i += NT) {
        int m = i >> 5, c = (i & 31) << 2;
        cpa(sb + (uint32_t)(XS_OFF + m * XPF + c) * 4, &x[(size_t)(b * SS + q0 + m) * DD + c], 16);
    }
    CP_COMMIT();

    // ---- W fp32 -> Wt fp16 transposed, straight from L2 ----
    {
        const float* Wg[3] = {Wq, Wk, Wv};
        const int    Wo[3] = {WT0_OFF, WT1_OFF, WT2_OFF};
        for (int wi = 0; wi < 3; wi++) {
            const float* Wf = Wg[wi];
            uint32_t* Wt = sm + Wo[wi];
            for (int i = tid; i < DD * 32; i += NT) {
                int n = i & 127, d4 = (i >> 7) << 2;
                float w0 = Wf[(d4 + 0) * DD + n];
                float w1 = Wf[(d4 + 1) * DD + n];
                float w2 = Wf[(d4 + 2) * DD + n];
                float w3 = Wf[(d4 + 3) * DD + n];
                uint2 pk = make_uint2(pkh(w0, w1), pkh(w2, w3));
                *(uint2*)&Wt[n * HP + (d4 >> 1)] = pk;
            }
        }
    }
    CP_WAIT(0);
    __syncthreads();           // Xs + all Wt ready

    // ---- A fragments (fp16-packed) cached for Q/K/V MMAs ----
    uint32_t a_all[8][4];
    {
        const float* Xs = (const float*)(sm + XS_OFF);
        #pragma unroll
        for (int ks = 0; ks < 8; ks++) {
            const int k0 = 16 * ks;
            float2 v0 = *(const float2*)&Xs[(r0 + gy) * XPF + k0 + 2 * gx];
            float2 v1 = *(const float2*)&Xs[(r0 + gy + 8) * XPF + k0 + 2 * gx];
            float2 v2 = *(const float2*)&Xs[(r0 + gy) * XPF + k0 + 8 + 2 * gx];
            float2 v3 = *(const float2*)&Xs[(r0 + gy + 8) * XPF + k0 + 8 + 2 * gx];
            a_all[ks][0] = pkh(v0.x, v0.y);
            a_all[ks][1] = pkh(v1.x, v1.y);
            a_all[ks][2] = pkh(v2.x, v2.y);
            a_all[ks][3] = pkh(v3.x, v3.y);
        }
    }

    auto run_mma = [&](int wt_off, float acc[8][4]) {
        const uint32_t* Wt = sm + wt_off;
        #pragma unroll
        for (int t = 0; t < 8; t++)
            #pragma unroll
            for (int c = 0; c < 4; c++) acc[t][c] = 0.f;
        #pragma unroll
        for (int ks = 0; ks < 8; ks++) {
            const int k0w = 8 * ks;
            #pragma unroll
            for (int t = 0; t < 8; t++) {
                int n0 = c0 + 8 * t;
                uint32_t b0 = Wt[(n0 + gy) * HP + k0w + gx];
                uint32_t b1 = Wt[(n0 + gy) * HP + k0w + 4 + gx];
                mma16(acc[t], a_all[ks], b0, b1);
            }
        }
    };

    const float scale = 0.088388347648318447f;  // 1/sqrt(128)
    float acc[8][4];

    // ---- Q projection -> Qh smem only (never global) ----
    run_mma(WT0_OFF, acc);
    __syncthreads();           // all warps done with Wt0 before Qh overwrite
    #pragma unroll
    for (int t = 0; t < 8; t++) {
        int col = c0 + 8 * t + 2 * gx;
        float bx = bq[col], by = bq[col + 1];
        sm[QH_OFF + (r0 + gy) * HP + (col >> 1)]     = pkh((acc[t][0] + bx) * scale, (acc[t][1] + by) * scale);
        sm[QH_OFF + (r0 + gy + 8) * HP + (col >> 1)] = pkh((acc[t][2] + bx) * scale, (acc[t][3] + by) * scale);
    }

    // ---- K projection -> Kh center + g_k ----
    run_mma(WT1_OFF, acc);
    #pragma unroll
    for (int t = 0; t < 8; t++) {
        int col = c0 + 8 * t + 2 * gx;
        float bx = bk[col], by = bk[col + 1];
        uint32_t p0 = pkh(acc[t][0] + bx, acc[t][1] + by);
        uint32_t p1 = pkh(acc[t][2] + bx, acc[t][3] + by);
        sm[KH_OFF + (64 + r0 + gy) * HP + (col >> 1)]     = p0;
        sm[KH_OFF + (64 + r0 + gy + 8) * HP + (col >> 1)] = p1;
        *(uint32_t*)&g_k[(size_t)(b * SS + q0 + r0 + gy) * DD + col]     = p0;
        *(uint32_t*)&g_k[(size_t)(b * SS + q0 + r0 + gy + 8) * DD + col] = p1;
    }
    __syncthreads();           // Wt1 (+Wt0 tail) free before Vt overwrite

    // ---- V projection -> Vt center + g_vt ----
    run_mma(WT2_OFF, acc);
    {
        __half* VtH = (__half*)(sm + VT_OFF);
        __half* vt  = g_vt + (size_t)b * DD * SS;
        const int s0 = r0 + gy;
        #pragma unroll
        for (int t = 0; t < 8; t++) {
            int col = c0 + 8 * t + 2 * gx;
            float bx = bv[col], by = bv[col + 1];
            __half h00 = __float2half_rn(acc[t][0] + bx);
            __half h01 = __float2half_rn(acc[t][1] + by);
            __half h10 = __float2half_rn(acc[t][2] + bx);
            __half h11 = __float2half_rn(acc[t][3] + by);
            VtH[(col)     * 2 * VTP + 64 + s0]     = h00;
            VtH[(col + 1) * 2 * VTP + 64 + s0]     = h01;
            VtH[(col)     * 2 * VTP + 64 + s0 + 8] = h10;
            VtH[(col + 1) * 2 * VTP + 64 + s0 + 8] = h11;
            vt[(size_t)(col)     * SS + q0 + s0]     = h00;
            vt[(size_t)(col + 1) * SS + q0 + s0]     = h01;
            vt[(size_t)(col)     * SS + q0 + s0 + 8] = h10;
            vt[(size_t)(col + 1) * SS + q0 + s0 + 8] = h11;
        }
    }

    // ---- publish + neighbor handshake ----
    __threadfence();
    __syncthreads();
    if (tid == 0) {
        int nc = (tb > 0) + (tb < 63);
        atomicAdd(&g_flag[blockIdx.x], nc);
        volatile int* vf = g_flag;
        if (tb > 0)  while (vf[blockIdx.x - 1] < 1) {}
        if (tb < 63) while (vf[blockIdx.x + 1] < 1) {}
    }
    __syncthreads();
    __threadfence();

    // ---- halo cp.async: K rows [0,64)+[128,192), Vt cols [0,64)+[128,192) ----
    for (int i = tid; i < 128 * 16; i += NT) {
        int hr = i >> 4, ci = i & 15;
        int j = hr < 64 ? hr : hr + 64;
        int key = kb + j;
        int ok = (key >= 0 && key < SS);
        cpa(sb + (uint32_t)(KH_OFF + j * HP + 4 * ci) * 4,
            g_k + ((size_t)b * SS + (ok ? key : 0)) * DD + 8 * ci, ok ? 16 : 0);
    }
    CP_COMMIT();
    for (int i = tid; i < 128 * 16; i += NT) {
        int d = i >> 4, ci = i & 15;
        int j0 = ci < 8 ? 8 * ci : 64 + 8 * ci;
        int key0 = kb + j0;
        int ok = (key0 >= 0 && key0 < SS);
        cpa(sb + (uint32_t)(VT_OFF + d * VTP + (j0 >> 1)) * 4,
            g_vt + ((size_t)b * DD + d) * SS + (ok ? key0 : 0), ok ? 16 : 0);
    }
    CP_COMMIT();
    CP_WAIT(1);                // K halos landed (V still streaming)
    __syncthreads();

    const int half = w >> 2;
    const int nb   = r0 + 72 * half;
    const uint32_t* Qu = sm + QH_OFF;
    const uint32_t* Ku = sm + KH_OFF;
    uint32_t*       Pu = sm + PH_OFF;
    float*          rs = (float*)(sm + RS_OFF);

    // ---- MMA1: S = Q K^T, m16 x n72 per warp, prefetch 1 k-step ----
    {
        float sacc[9][4];
        #pragma unroll
        for (int t = 0; t < 9; t++)
            #pragma unroll
            for (int c = 0; c < 4; c++) sacc[t][c] = 0.f;

        uint32_t ap[4], bp[9][2];
        ap[0] = Qu[(r0 + gy) * HP + gx];
        ap[1] = Qu[(r0 + gy + 8) * HP + gx];
        ap[2] = Qu[(r0 + gy) * HP + 4 + gx];
        ap[3] = Qu[(r0 + gy + 8) * HP + 4 + gx];
        #pragma unroll
        for (int t = 0; t < 9; t++) {
            int n0 = nb + 8 * t;
            bp[t][0] = Ku[(n0 + gy) * HP + gx];
            bp[t][1] = Ku[(n0 + gy) * HP + 4 + gx];
        }
        #pragma unroll
        for (int ks = 0; ks < 8; ks++) {
            uint32_t an[4], bn[9][2];
            if (ks < 7) {
                const int k1w = 8 * (ks + 1);
                an[0] = Qu[(r0 + gy) * HP + k1w + gx];
                an[1] = Qu[(r0 + gy + 8) * HP + k1w + gx];
                an[2] = Qu[(r0 + gy) * HP + k1w + 4 + gx];
                an[3] = Qu[(r0 + gy + 8) * HP + k1w + 4 + gx];
                #pragma unroll
                for (int t = 0; t < 9; t++) {
                    int n0 = nb + 8 * t;
                    bn[t][0] = Ku[(n0 + gy) * HP + k1w + gx];
                    bn[t][1] = Ku[(n0 + gy) * HP + k1w + 4 + gx];
                }
            }
            #pragma unroll
            for (int t = 0; t < 9; t++) mma16(sacc[t], ap, bp[t][0], bp[t][1]);
            if (ks < 7) {
                #pragma unroll
                for (int q = 0; q < 4; q++) ap[q] = an[q];
                #pragma unroll
                for (int t = 0; t < 9; t++) { bp[t][0] = bn[t][0]; bp[t][1] = bn[t][1]; }
            }
        }

        // mask + exp in registers; fp16 P; unique-writer row sums
        float part[2] = {0.f, 0.f};
        #pragma unroll
        for (int t = 0; t < 9; t++) {
            #pragma unroll
            for (int h = 0; h < 2; h++) {
                int q  = r0 + gy + 8 * h;
                int j0 = nb + 8 * t + 2 * gx;
                float p0 = 0.f, p1 = 0.f;
                {
                    int j = j0, key = kb + j, dj = j - q;
                    if (dj >= 0 && dj <= 2 * HALF && key >= 0 && key < SS)
                        p0 = __expf(sacc[t][2 * h]);
                }
                {
                    int j = j0 + 1, key = kb + j, dj = j - q;
                    if (dj >= 0 && dj <= 2 * HALF && key >= 0 && key < SS)
                        p1 = __expf(sacc[t][2 * h + 1]);
                }
                part[h] += p0 + p1;
                Pu[q * VTP + (j0 >> 1)] = pkh(p0, p1);
            }
        }
        #pragma unroll
        for (int h = 0; h < 2; h++) {
            part[h] += __shfl_xor_sync(0xffffffffu, part[h], 1);
            part[h] += __shfl_xor_sync(0xffffffffu, part[h], 2);
        }
        if (gx == 0) {
            rs[64 * half + r0 + gy]     = part[0];
            rs[64 * half + r0 + gy + 8] = part[1];
        }
    }
    __syncthreads();
    CP_WAIT(0);                // V halos landed
    __syncthreads();
    if (tid == 0) {            // halos consumed: reset neighbor flags for replay
        if (tb > 0)  atomicSub(&g_flag[blockIdx.x - 1], 1);
        if (tb < 63) atomicSub(&g_flag[blockIdx.x + 1], 1);
    }

    // ---- MMA2: O = (P V) * inv, m16 x n64 per warp, 9 band k-steps ----
    {
        const uint32_t* Vu = sm + VT_OFF;
        const int d0 = 64 * half;
        float oacc[8][4];
        #pragma unroll
        for (int t = 0; t < 8; t++)
            #pragma unroll
            for (int c = 0; c < 4; c++) oacc[t][c] = 0.f;

        const int kw0 = r0 >> 1;
        uint32_t ap[4], bp[8][2];
        ap[0] = Pu[(r0 + gy) * VTP + kw0 + gx];
        ap[1] = Pu[(r0 + gy + 8) * VTP + kw0 + gx];
        ap[2] = Pu[(r0 + gy) * VTP + kw0 + 4 + gx];
        ap[3] = Pu[(r0 + gy + 8) * VTP + kw0 + 4 + gx];
        #pragma unroll
        for (int t = 0; t < 8; t++) {
            int n0 = d0 + 8 * t;
            bp[t][0] = Vu[(n0 + gy) * VTP + kw0 + gx];
            bp[t][1] = Vu[(n0 + gy) * VTP + kw0 + 4 + gx];
        }
        #pragma unroll
        for (int ks = 0; ks < 9; ks++) {
            uint32_t an[4], bn[8][2];
            if (ks < 8) {
                const int k1w = kw0 + 8 * (ks + 1);
                an[0] = Pu[(r0 + gy) * VTP + k1w + gx];
                an[1] = Pu[(r0 + gy + 8) * VTP + k1w + gx];
                an[2] = Pu[(r0 + gy) * VTP + k1w + 4 + gx];
                an[3] = Pu[(r0 + gy + 8) * VTP + k1w + 4 + gx];
                #pragma unroll
                for (int t = 0; t < 8; t++) {
                    int n0 = d0 + 8 * t;
                    bn[t][0] = Vu[(n0 + gy) * VTP + k1w + gx];
                    bn[t][1] = Vu[(n0 + gy) * VTP + k1w + 4 + gx];
                }
            }
            #pragma unroll
            for (int t = 0; t < 8; t++) mma16(oacc[t], ap, bp[t][0], bp[t][1]);
            if (ks < 8) {
                #pragma unroll
                for (int q = 0; q < 4; q++) ap[q] = an[q];
                #pragma unroll
                for (int t = 0; t < 8; t++) { bp[t][0] = bn[t][0]; bp[t][1] = bn[t][1]; }
            }
        }

        const float inv0 = 1.f / (rs[r0 + gy] + rs[64 + r0 + gy]);
        const float inv1 = 1.f / (rs[r0 + gy + 8] + rs[64 + r0 + gy + 8]);
        float* ob = out + (size_t)(b * SS + q0) * DD;
        #pragma unroll
        for (int t = 0; t < 8; t++) {
            int col = d0 + 8 * t + 2 * gx;
            *(float2*)&ob[(r0 + gy) * DD + col]     = make_float2(oacc[t][0] * inv0, oacc[t][1] * inv0);
            *(float2*)&ob[(r0 + gy + 8) * DD + col] = make_float2(oacc[t][2] * inv1, oacc[t][3] * inv1);
        }
    }
}

// ---------------------------------------------------------------------------
extern "C" void kernel_launch(void* const* d_in, const int* in_sizes, int n_in,
                              void* d_out, int out_size)
{
    const float* x  = (const float*)d_in[0];
    const float* Wq = (const float*)d_in[1];
    const float* bq = (const float*)d_in[2];
    const float* Wk = (const float*)d_in[3];
    const float* bk = (const float*)d_in[4];
    const float* Wv = (const float*)d_in[5];
    const float* bv = (const float*)d_in[6];
    float* out = (float*)d_out;

    cudaFuncSetAttribute(fused_kernel, cudaFuncAttributeMaxDynamicSharedMemorySize, SMEM_BYTES);
    fused_kernel<<<BB * (SS / TM), NT, SMEM_BYTES>>>(x, Wq, bq, Wk, bk, Wv, bv, out);
}